// round 16
// baseline (speedup 1.0000x reference)
#include <cuda_runtime.h>
#include <cuda_fp16.h>
#include <cstdint>
#include <cstddef>

// ============================================================================
// MoE FFN, sm_103 baseline. fp16 mma.sync m16n8k16, BK=64, trans-ldmatrix B,
// R12 barrier-ahead pipeline.
// R16: gemm2 retiled to 64x128 (2048 CTAs -> ~99% wave efficiency vs 86%),
//      single merged pre-pass kernel, streams dropped (proven zero-sum).
//   PRE  : h, W1, W2 -> fp16 in ONE kernel
//   G1A  : act = fp16(up * relu(gate))   (fused epilogue)
//   GEMM2: out = act @ W2
// ============================================================================

#define KD 2048

__device__ __half g_act[8192ull * 2048ull];          //  33 MB
__device__ __half g_hh [8192ull * 2048ull];          //  33 MB
__device__ __half g_w1h[8ull * 2048ull * 4096ull];   // 134 MB W1 [E][K][4096]
__device__ __half g_w2h[8ull * 2048ull * 2048ull];   //  67 MB W2 [E][K][2048]

static constexpr int STRIDE_H = 72;                  // halves
static constexpr int ROW_A    = STRIDE_H * 2;        // 144 B
static constexpr int TILE_A   = 128 * ROW_A;         // 18432 (gemm1: 128 rows)
static constexpr int ROW_BB   = 272;                 // 128 halves + 16B pad
static constexpr int TILE_BB  = 64 * ROW_BB;         // 17408
static constexpr int STAGE_B  = TILE_A + TILE_BB;    // 35840
static constexpr int STAGES   = 3;
static constexpr int SMEM_TOTAL = STAGE_B * STAGES;  // 107520
// gemm2 (64-row A tile):
static constexpr int TILE_A2  = 64 * ROW_A;          // 9216
static constexpr int STAGE_B2 = TILE_A2 + TILE_BB;   // 26624
static constexpr int SMEM_TOTAL2 = STAGE_B2 * STAGES; // 79872

__device__ __forceinline__ uint32_t smem_u32(const void* p) {
    uint32_t a;
    asm("{ .reg .u64 t; cvta.to.shared.u64 t, %1; cvt.u32.u64 %0, t; }"
        : "=r"(a) : "l"(p));
    return a;
}

#define CP16(d, s) asm volatile("cp.async.cg.shared.global [%0], [%1], 16;" \
                                :: "r"(d), "l"(s))
#define CP_COMMIT() asm volatile("cp.async.commit_group;" ::: "memory")
#define CP_WAITG(n) asm volatile("cp.async.wait_group %0;" :: "n"(n) : "memory")

#define LDSM_X4(r0, r1, r2, r3, a) asm volatile(                             \
    "ldmatrix.sync.aligned.m8n8.x4.shared.b16 {%0,%1,%2,%3}, [%4];"          \
    : "=r"(r0), "=r"(r1), "=r"(r2), "=r"(r3) : "r"(a))

#define LDSM_X4_T(r0, r1, r2, r3, a) asm volatile(                           \
    "ldmatrix.sync.aligned.m8n8.x4.trans.shared.b16 {%0,%1,%2,%3}, [%4];"    \
    : "=r"(r0), "=r"(r1), "=r"(r2), "=r"(r3) : "r"(a))

__device__ __forceinline__ void mma_f16(float c[4], const uint32_t a[4],
                                        const uint32_t b[2]) {
    asm volatile(
        "mma.sync.aligned.m16n8k16.row.col.f32.f16.f16.f32 "
        "{%0,%1,%2,%3}, {%4,%5,%6,%7}, {%8,%9}, {%0,%1,%2,%3};"
        : "+f"(c[0]), "+f"(c[1]), "+f"(c[2]), "+f"(c[3])
        : "r"(a[0]), "r"(a[1]), "r"(a[2]), "r"(a[3]), "r"(b[0]), "r"(b[1]));
}

// A x4 (16 rows x 16 halves): {m-lo,k-lo},{m-hi,k-lo},{m-lo,k-hi},{m-hi,k-hi}
__device__ __forceinline__ uint32_t ldsm_offA(int lane) {
    const int r8 = lane & 7;
    return (uint32_t)(((((lane >> 3) & 1) * 8 + r8) * STRIDE_H
                       + (lane >> 4) * 8) * 2);
}
// B trans x4 ([k][n] storage): {k-lo,n-lo},{k-hi,n-lo},{k-lo,n-hi},{k-hi,n-hi}
__device__ __forceinline__ uint32_t ldsm_offB_T(int lane) {
    const int t = lane >> 3, r8 = lane & 7;
    return (uint32_t)(((t & 1) * 8 + r8) * ROW_BB + (t >> 1) * 8 * 2);
}

// ---- fragment macros, MI = number of 16-row A sub-tiles --------------------
#define LDFRAG_G(pb, ks, st, MI) do {                                        \
    const uint32_t _koA = (uint32_t)((ks) * 32);                             \
    const uint32_t _koB = (uint32_t)((ks) * 16 * ROW_BB);                    \
    _Pragma("unroll")                                                        \
    for (int _mi = 0; _mi < (MI); _mi++)                                     \
        LDSM_X4(af[pb][_mi][0], af[pb][_mi][1], af[pb][_mi][2],              \
                af[pb][_mi][3],                                              \
                (st) + abase + _koA + (uint32_t)(_mi * 16 * ROW_A));         \
    _Pragma("unroll")                                                        \
    for (int _b = 0; _b < 4; _b++)                                           \
        LDSM_X4_T(bf[pb][2 * _b][0], bf[pb][2 * _b][1],                      \
                  bf[pb][2 * _b + 1][0], bf[pb][2 * _b + 1][1],              \
                  (st) + bbase + _koB + (uint32_t)(_b * 32));                \
} while (0)

#define MMA_STEP_G(pb, MI) do {                                              \
    _Pragma("unroll")                                                        \
    for (int _mi = 0; _mi < (MI); _mi++)                                     \
        _Pragma("unroll")                                                    \
        for (int _ni = 0; _ni < 8; _ni++)                                    \
            mma_f16(acc[_mi][_ni], af[pb][_mi], bf[pb][_ni]);                \
} while (0)

// R12 barrier-ahead mainloop, parameterized by stage size and MI.
#define MAINLOOP_G(SB, MI)                                                   \
    load_stage(0, 0);                                                        \
    load_stage(1, 1);                                                        \
    for (int kt = 0; kt < NKT; kt++) {                                       \
        CP_WAITG(0);                                                         \
        __syncthreads();                                                     \
        if (kt + 2 < NKT) load_stage((kt + 2) % STAGES, kt + 2);             \
        const uint32_t st = sbase + (uint32_t)((kt % STAGES) * (SB));        \
        const uint32_t stn = sbase                                           \
            + (uint32_t)(((kt + 1) % STAGES) * (SB));                        \
        if (kt == 0) LDFRAG_G(0, 0, st, MI);                                 \
        _Pragma("unroll")                                                    \
        for (int ks = 0; ks < 4; ks++) {                                     \
            if (ks < 3) LDFRAG_G((ks + 1) & 1, ks + 1, st, MI);              \
            else if (kt + 1 < NKT) LDFRAG_G(0, 0, stn, MI);                  \
            MMA_STEP_G(ks & 1, MI);                                          \
        }                                                                    \
    }

// ---------------------------------------------------------------------------
// GEMM1 fused with activation. CTA 128 tokens x 64 act cols; warps 2Mx2N.
// ---------------------------------------------------------------------------
__global__ void __launch_bounds__(128, 2)
gemm1_act(const __half* __restrict__ X, const __half* __restrict__ W1h,
          __half* __restrict__ Act)
{
    extern __shared__ __align__(16) char smem[];
    const int tid = threadIdx.x;
    const int wid = tid >> 5, lane = tid & 31;
    const int g = lane >> 2, tg = lane & 3;
    const int wm = wid & 1, wn = wid >> 1;
    const int nt = blockIdx.x, tt = blockIdx.y, e = blockIdx.z;

    const __half* Ag = X + (size_t)(e * 1024 + tt * 128) * KD;
    const uint32_t sbase = smem_u32(smem);

    const int cr = tid >> 3, cc = tid & 7;          // A: 16 rows/pass
    const uint32_t cdstA = (uint32_t)(cr * ROW_A + cc * 16);
    const int cr2 = tid >> 4, cc2 = tid & 15;       // B: 8 k-rows/pass
    const uint32_t cdstB = (uint32_t)(cr2 * ROW_BB + cc2 * 16);
    const int ncol = nt * 64 + (cc2 & 7) * 8 + ((cc2 >= 8) ? 2048 : 0);
    const __half* Bg = W1h + (size_t)e * KD * 4096 + ncol;

    auto load_stage = [&](int buf, int kt) {
        const uint32_t sa = sbase + (uint32_t)buf * STAGE_B;
        const uint32_t sb = sa + TILE_A;
        const __half* a = Ag + kt * 64;
#pragma unroll
        for (int j = 0; j < 8; j++)
            CP16(sa + cdstA + (uint32_t)(j * 16 * ROW_A),
                 a + (size_t)(cr + j * 16) * KD + cc * 8);
        const __half* b = Bg + (size_t)(kt * 64 + cr2) * 4096;
#pragma unroll
        for (int j = 0; j < 8; j++)
            CP16(sb + cdstB + (uint32_t)(j * 8 * ROW_BB),
                 b + (size_t)(j * 8) * 4096);
        CP_COMMIT();
    };

    const uint32_t abase = (uint32_t)(wm * 64 * ROW_A) + ldsm_offA(lane);
    const uint32_t bbase = (uint32_t)(wn * 128) + ldsm_offB_T(lane) + TILE_A;

    float acc[4][8][4];
#pragma unroll
    for (int mi = 0; mi < 4; mi++)
#pragma unroll
        for (int ni = 0; ni < 8; ni++)
#pragma unroll
            for (int q = 0; q < 4; q++) acc[mi][ni][q] = 0.f;

    uint32_t af[2][4][4], bf[2][8][2];
    constexpr int NKT = KD / 64;   // 32
    MAINLOOP_G(STAGE_B, 4);

    // ---- fused act epilogue (stride 66 f32, 8B-aligned float2) ----------
    __syncthreads();
    float* ex = reinterpret_cast<float*>(smem) + wm * (64 * 66);
    if (wn == 1) {                         // up warps publish
#pragma unroll
        for (int mi = 0; mi < 4; mi++) {
            const int r0 = mi * 16 + g;
#pragma unroll
            for (int ni = 0; ni < 8; ni++) {
                const int cb = ni * 8 + tg * 2;
                *reinterpret_cast<float2*>(ex + r0 * 66 + cb) =
                    make_float2(acc[mi][ni][0], acc[mi][ni][1]);
                *reinterpret_cast<float2*>(ex + (r0 + 8) * 66 + cb) =
                    make_float2(acc[mi][ni][2], acc[mi][ni][3]);
            }
        }
    }
    __syncthreads();
    if (wn == 0) {                         // gate warps combine + store
        __half* Og = Act + (size_t)(e * 1024 + tt * 128 + wm * 64) * 2048
                   + nt * 64;
#pragma unroll
        for (int mi = 0; mi < 4; mi++) {
            const int r0 = mi * 16 + g;
#pragma unroll
            for (int ni = 0; ni < 8; ni++) {
                const int cb = ni * 8 + tg * 2;
                const float2 ulo = *reinterpret_cast<float2*>(ex + r0 * 66 + cb);
                const float2 uhi =
                    *reinterpret_cast<float2*>(ex + (r0 + 8) * 66 + cb);
                __half2 lo = __floats2half2_rn(
                    ulo.x * fmaxf(acc[mi][ni][0], 0.f),
                    ulo.y * fmaxf(acc[mi][ni][1], 0.f));
                __half2 hi = __floats2half2_rn(
                    uhi.x * fmaxf(acc[mi][ni][2], 0.f),
                    uhi.y * fmaxf(acc[mi][ni][3], 0.f));
                *reinterpret_cast<uint32_t*>(Og + (size_t)r0 * 2048 + cb) =
                    *reinterpret_cast<uint32_t*>(&lo);
                *reinterpret_cast<uint32_t*>(Og + (size_t)(r0 + 8) * 2048 + cb) =
                    *reinterpret_cast<uint32_t*>(&hi);
            }
        }
    }
}

// ---------------------------------------------------------------------------
// GEMM2: 64x128 CTA tile (2048 CTAs -> ~99% wave eff), warps 2Mx2N
// (warp tile 32x64), fp32 out.
// ---------------------------------------------------------------------------
__global__ void __launch_bounds__(128, 2)
gemm2(const __half* __restrict__ X, const __half* __restrict__ W2h,
      float* __restrict__ C)
{
    extern __shared__ __align__(16) char smem[];
    const int tid = threadIdx.x;
    const int wid = tid >> 5, lane = tid & 31;
    const int g = lane >> 2, tg = lane & 3;
    const int wm = wid & 1, wn = wid >> 1;
    const int nt = blockIdx.x, tt = blockIdx.y, e = blockIdx.z;
    constexpr int WN = 2048;

    const __half* Ag = X + (size_t)(e * 1024 + tt * 64) * KD;
    const uint32_t sbase = smem_u32(smem);

    // A: 64 rows x 8 chunks = 512 cp / 128 thr = 4/thread
    const int cr = tid >> 3, cc = tid & 7;          // 16 rows/pass
    const uint32_t cdstA = (uint32_t)(cr * ROW_A + cc * 16);
    const int cr2 = tid >> 4, cc2 = tid & 15;       // B: 8 k-rows/pass
    const uint32_t cdstB = (uint32_t)(cr2 * ROW_BB + cc2 * 16);
    const __half* Bg = W2h + (size_t)e * KD * WN + nt * 128 + cc2 * 8;

    auto load_stage = [&](int buf, int kt) {
        const uint32_t sa = sbase + (uint32_t)buf * STAGE_B2;
        const uint32_t sb = sa + TILE_A2;
        const __half* a = Ag + kt * 64;
#pragma unroll
        for (int j = 0; j < 4; j++)
            CP16(sa + cdstA + (uint32_t)(j * 16 * ROW_A),
                 a + (size_t)(cr + j * 16) * KD + cc * 8);
        const __half* b = Bg + (size_t)(kt * 64 + cr2) * WN;
#pragma unroll
        for (int j = 0; j < 8; j++)
            CP16(sb + cdstB + (uint32_t)(j * 8 * ROW_BB),
                 b + (size_t)(j * 8) * WN);
        CP_COMMIT();
    };

    const uint32_t abase = (uint32_t)(wm * 32 * ROW_A) + ldsm_offA(lane);
    const uint32_t bbase = (uint32_t)(wn * 128) + ldsm_offB_T(lane) + TILE_A2;

    float acc[2][8][4];
#pragma unroll
    for (int mi = 0; mi < 2; mi++)
#pragma unroll
        for (int ni = 0; ni < 8; ni++)
#pragma unroll
            for (int q = 0; q < 4; q++) acc[mi][ni][q] = 0.f;

    uint32_t af[2][2][4], bf[2][8][2];
    constexpr int NKT = KD / 64;   // 32
    MAINLOOP_G(STAGE_B2, 2);

    float* Cg = C + (size_t)(e * 1024 + tt * 64) * WN + nt * 128;
#pragma unroll
    for (int mi = 0; mi < 2; mi++) {
        const int r0 = wm * 32 + mi * 16 + g;
#pragma unroll
        for (int ni = 0; ni < 8; ni++) {
            const int cb = wn * 64 + ni * 8 + tg * 2;
            float2 lo = make_float2(acc[mi][ni][0], acc[mi][ni][1]);
            float2 hi = make_float2(acc[mi][ni][2], acc[mi][ni][3]);
            *reinterpret_cast<float2*>(Cg + (size_t)r0 * WN + cb) = lo;
            *reinterpret_cast<float2*>(Cg + (size_t)(r0 + 8) * WN + cb) = hi;
        }
    }
}

// ---------------------------------------------------------------------------
// Merged pre-pass: rounds h, W1, W2 to fp16 in one launch.
// ---------------------------------------------------------------------------
static constexpr size_t N4_H  = 8192ull * 2048 / 4;          //  4194304
static constexpr size_t N4_W1 = 8ull * 2048 * 4096 / 4;      // 16777216
static constexpr size_t N4_W2 = 8ull * 2048 * 2048 / 4;      //  8388608
static constexpr size_t N4_ALL = N4_H + N4_W1 + N4_W2;       // 29360128

__global__ void __launch_bounds__(256)
round_all(__half* __restrict__ hh, const float* __restrict__ h,
          __half* __restrict__ w1h, const float* __restrict__ w1,
          __half* __restrict__ w2h, const float* __restrict__ w2)
{
    size_t i = (size_t)blockIdx.x * blockDim.x + threadIdx.x;   // f4 index
    const float* src;
    __half* dst;
    if (i < N4_H)            { src = h;  dst = hh; }
    else if (i < N4_H + N4_W1) { src = w1; dst = w1h; i -= N4_H; }
    else                     { src = w2; dst = w2h; i -= N4_H + N4_W1; }
    const float4 v = *reinterpret_cast<const float4*>(src + i * 4);
    __half2 lo = __floats2half2_rn(v.x, v.y);
    __half2 hi = __floats2half2_rn(v.z, v.w);
    uint2 o = make_uint2(*reinterpret_cast<uint32_t*>(&lo),
                         *reinterpret_cast<uint32_t*>(&hi));
    *reinterpret_cast<uint2*>(dst + i * 4) = o;
}

extern "C" void kernel_launch(void* const* d_in, const int* in_sizes, int n_in,
                              void* d_out, int out_size) {
    (void)in_sizes; (void)n_in; (void)out_size;
    const float* h  = (const float*)d_in[0];
    const float* w1 = (const float*)d_in[1];
    const float* w2 = (const float*)d_in[2];
    float* out = (float*)d_out;

    __half *act, *hh, *w1h, *w2h;
    cudaGetSymbolAddress((void**)&act, g_act);
    cudaGetSymbolAddress((void**)&hh,  g_hh);
    cudaGetSymbolAddress((void**)&w1h, g_w1h);
    cudaGetSymbolAddress((void**)&w2h, g_w2h);

    cudaFuncSetAttribute(gemm1_act,
                         cudaFuncAttributeMaxDynamicSharedMemorySize, SMEM_TOTAL);
    cudaFuncSetAttribute(gemm2,
                         cudaFuncAttributeMaxDynamicSharedMemorySize, SMEM_TOTAL2);

    round_all<<<(unsigned)(N4_ALL / 256), 256>>>(hh, h, w1h, w1, w2h, w2);
    gemm1_act<<<dim3(32, 8, 8), 128, SMEM_TOTAL>>>(hh, w1h, act);
    gemm2<<<dim3(16, 16, 8), 128, SMEM_TOTAL2>>>(act, w2h, out);
}

// round 17
// speedup vs baseline: 1.0325x; 1.0325x over previous
#include <cuda_runtime.h>
#include <cuda_fp16.h>
#include <cstdint>
#include <cstddef>

// ============================================================================
// MoE FFN, sm_103 baseline. fp16 mma.sync m16n8k16, BK=64, trans-ldmatrix B,
// R12 barrier-ahead pipeline.
// R17 = R12 GEMM config (both GEMMs 128x128 CTA tile, warp 64x64, 2 CTAs/SM)
//       + merged single pre-pass kernel (at the DRAM floor).
//   PRE  : h, W1, W2 -> fp16 in ONE kernel
//   G1A  : act = fp16(up * relu(gate))   (fused epilogue)
//   GEMM2: out = act @ W2
// ============================================================================

#define KD 2048

__device__ __half g_act[8192ull * 2048ull];          //  33 MB
__device__ __half g_hh [8192ull * 2048ull];          //  33 MB
__device__ __half g_w1h[8ull * 2048ull * 4096ull];   // 134 MB W1 [E][K][4096]
__device__ __half g_w2h[8ull * 2048ull * 2048ull];   //  67 MB W2 [E][K][2048]

static constexpr int STRIDE_H = 72;                  // halves
static constexpr int ROW_A    = STRIDE_H * 2;        // 144 B
static constexpr int TILE_A   = 128 * ROW_A;         // 18432
static constexpr int ROW_BB   = 272;                 // 128 halves + 16B pad
static constexpr int TILE_BB  = 64 * ROW_BB;         // 17408
static constexpr int STAGE_B  = TILE_A + TILE_BB;    // 35840
static constexpr int STAGES   = 3;
static constexpr int SMEM_TOTAL = STAGE_B * STAGES;  // 107520

__device__ __forceinline__ uint32_t smem_u32(const void* p) {
    uint32_t a;
    asm("{ .reg .u64 t; cvta.to.shared.u64 t, %1; cvt.u32.u64 %0, t; }"
        : "=r"(a) : "l"(p));
    return a;
}

#define CP16(d, s) asm volatile("cp.async.cg.shared.global [%0], [%1], 16;" \
                                :: "r"(d), "l"(s))
#define CP_COMMIT() asm volatile("cp.async.commit_group;" ::: "memory")
#define CP_WAITG(n) asm volatile("cp.async.wait_group %0;" :: "n"(n) : "memory")

#define LDSM_X4(r0, r1, r2, r3, a) asm volatile(                             \
    "ldmatrix.sync.aligned.m8n8.x4.shared.b16 {%0,%1,%2,%3}, [%4];"          \
    : "=r"(r0), "=r"(r1), "=r"(r2), "=r"(r3) : "r"(a))

#define LDSM_X4_T(r0, r1, r2, r3, a) asm volatile(                           \
    "ldmatrix.sync.aligned.m8n8.x4.trans.shared.b16 {%0,%1,%2,%3}, [%4];"    \
    : "=r"(r0), "=r"(r1), "=r"(r2), "=r"(r3) : "r"(a))

__device__ __forceinline__ void mma_f16(float c[4], const uint32_t a[4],
                                        const uint32_t b[2]) {
    asm volatile(
        "mma.sync.aligned.m16n8k16.row.col.f32.f16.f16.f32 "
        "{%0,%1,%2,%3}, {%4,%5,%6,%7}, {%8,%9}, {%0,%1,%2,%3};"
        : "+f"(c[0]), "+f"(c[1]), "+f"(c[2]), "+f"(c[3])
        : "r"(a[0]), "r"(a[1]), "r"(a[2]), "r"(a[3]), "r"(b[0]), "r"(b[1]));
}

// A x4 (16 rows x 16 halves): {m-lo,k-lo},{m-hi,k-lo},{m-lo,k-hi},{m-hi,k-hi}
__device__ __forceinline__ uint32_t ldsm_offA(int lane) {
    const int r8 = lane & 7;
    return (uint32_t)(((((lane >> 3) & 1) * 8 + r8) * STRIDE_H
                       + (lane >> 4) * 8) * 2);
}
// B trans x4 ([k][n] storage): {k-lo,n-lo},{k-hi,n-lo},{k-lo,n-hi},{k-hi,n-hi}
__device__ __forceinline__ uint32_t ldsm_offB_T(int lane) {
    const int t = lane >> 3, r8 = lane & 7;
    return (uint32_t)(((t & 1) * 8 + r8) * ROW_BB + (t >> 1) * 8 * 2);
}

// load fragments for (stage st, k-slice ks) into rotating buffer pb
#define LDFRAG(pb, ks, st) do {                                              \
    const uint32_t _koA = (uint32_t)((ks) * 32);                             \
    const uint32_t _koB = (uint32_t)((ks) * 16 * ROW_BB);                    \
    _Pragma("unroll")                                                        \
    for (int _mi = 0; _mi < 4; _mi++)                                        \
        LDSM_X4(af[pb][_mi][0], af[pb][_mi][1], af[pb][_mi][2],              \
                af[pb][_mi][3],                                              \
                (st) + abase + _koA + (uint32_t)(_mi * 16 * ROW_A));         \
    _Pragma("unroll")                                                        \
    for (int _b = 0; _b < 4; _b++)                                           \
        LDSM_X4_T(bf[pb][2 * _b][0], bf[pb][2 * _b][1],                      \
                  bf[pb][2 * _b + 1][0], bf[pb][2 * _b + 1][1],              \
                  (st) + bbase + _koB + (uint32_t)(_b * 32));                \
} while (0)

#define MMA_STEP(pb) do {                                                    \
    _Pragma("unroll")                                                        \
    for (int _mi = 0; _mi < 4; _mi++)                                        \
        _Pragma("unroll")                                                    \
        for (int _ni = 0; _ni < 8; _ni++)                                    \
            mma_f16(acc[_mi][_ni], af[pb][_mi], bf[pb][_ni]);                \
} while (0)

// R12 mainloop: top-of-kt waits ALL in-flight cp.async then syncs — this
// makes BOTH stage kt and stage kt+1 visible to every thread, so the seam
// prefetch of stage kt+1's ks0 at ks3 is race-free.
#define MAINLOOP()                                                           \
    load_stage(0, 0);                                                        \
    load_stage(1, 1);                                                        \
    for (int kt = 0; kt < NKT; kt++) {                                       \
        CP_WAITG(0);                                                         \
        __syncthreads();                                                     \
        if (kt + 2 < NKT) load_stage((kt + 2) % STAGES, kt + 2);             \
        const uint32_t st = sbase + (uint32_t)((kt % STAGES) * STAGE_B);     \
        const uint32_t stn = sbase                                           \
            + (uint32_t)(((kt + 1) % STAGES) * STAGE_B);                     \
        if (kt == 0) LDFRAG(0, 0, st);                                       \
        _Pragma("unroll")                                                    \
        for (int ks = 0; ks < 4; ks++) {                                     \
            if (ks < 3) LDFRAG((ks + 1) & 1, ks + 1, st);                    \
            else if (kt + 1 < NKT) LDFRAG(0, 0, stn);                        \
            MMA_STEP(ks & 1);                                                \
        }                                                                    \
    }

// ---------------------------------------------------------------------------
// GEMM1 fused with activation. CTA 128 tokens x 64 act cols; warps 2Mx2N.
// B tile n 0-63 = gate cols, n 64-127 = up cols (+2048 in W1).
// ---------------------------------------------------------------------------
__global__ void __launch_bounds__(128, 2)
gemm1_act(const __half* __restrict__ X, const __half* __restrict__ W1h,
          __half* __restrict__ Act)
{
    extern __shared__ __align__(16) char smem[];
    const int tid = threadIdx.x;
    const int wid = tid >> 5, lane = tid & 31;
    const int g = lane >> 2, tg = lane & 3;
    const int wm = wid & 1, wn = wid >> 1;
    const int nt = blockIdx.x, tt = blockIdx.y, e = blockIdx.z;

    const __half* Ag = X + (size_t)(e * 1024 + tt * 128) * KD;
    const uint32_t sbase = smem_u32(smem);

    const int cr = tid >> 3, cc = tid & 7;          // A: 16 rows/pass
    const uint32_t cdstA = (uint32_t)(cr * ROW_A + cc * 16);
    const int cr2 = tid >> 4, cc2 = tid & 15;       // B: 8 k-rows/pass
    const uint32_t cdstB = (uint32_t)(cr2 * ROW_BB + cc2 * 16);
    const int ncol = nt * 64 + (cc2 & 7) * 8 + ((cc2 >= 8) ? 2048 : 0);
    const __half* Bg = W1h + (size_t)e * KD * 4096 + ncol;

    auto load_stage = [&](int buf, int kt) {
        const uint32_t sa = sbase + (uint32_t)buf * STAGE_B;
        const uint32_t sb = sa + TILE_A;
        const __half* a = Ag + kt * 64;
#pragma unroll
        for (int j = 0; j < 8; j++)
            CP16(sa + cdstA + (uint32_t)(j * 16 * ROW_A),
                 a + (size_t)(cr + j * 16) * KD + cc * 8);
        const __half* b = Bg + (size_t)(kt * 64 + cr2) * 4096;
#pragma unroll
        for (int j = 0; j < 8; j++)
            CP16(sb + cdstB + (uint32_t)(j * 8 * ROW_BB),
                 b + (size_t)(j * 8) * 4096);
        CP_COMMIT();
    };

    const uint32_t abase = (uint32_t)(wm * 64 * ROW_A) + ldsm_offA(lane);
    const uint32_t bbase = (uint32_t)(wn * 128) + ldsm_offB_T(lane) + TILE_A;

    float acc[4][8][4];
#pragma unroll
    for (int mi = 0; mi < 4; mi++)
#pragma unroll
        for (int ni = 0; ni < 8; ni++)
#pragma unroll
            for (int q = 0; q < 4; q++) acc[mi][ni][q] = 0.f;

    uint32_t af[2][4][4], bf[2][8][2];
    constexpr int NKT = KD / 64;   // 32
    MAINLOOP();

    // ---- fused act epilogue (stride 66 f32, 8B-aligned float2) ----------
    __syncthreads();
    float* ex = reinterpret_cast<float*>(smem) + wm * (64 * 66);
    if (wn == 1) {                         // up warps publish
#pragma unroll
        for (int mi = 0; mi < 4; mi++) {
            const int r0 = mi * 16 + g;
#pragma unroll
            for (int ni = 0; ni < 8; ni++) {
                const int cb = ni * 8 + tg * 2;
                *reinterpret_cast<float2*>(ex + r0 * 66 + cb) =
                    make_float2(acc[mi][ni][0], acc[mi][ni][1]);
                *reinterpret_cast<float2*>(ex + (r0 + 8) * 66 + cb) =
                    make_float2(acc[mi][ni][2], acc[mi][ni][3]);
            }
        }
    }
    __syncthreads();
    if (wn == 0) {                         // gate warps combine + store
        __half* Og = Act + (size_t)(e * 1024 + tt * 128 + wm * 64) * 2048
                   + nt * 64;
#pragma unroll
        for (int mi = 0; mi < 4; mi++) {
            const int r0 = mi * 16 + g;
#pragma unroll
            for (int ni = 0; ni < 8; ni++) {
                const int cb = ni * 8 + tg * 2;
                const float2 ulo = *reinterpret_cast<float2*>(ex + r0 * 66 + cb);
                const float2 uhi =
                    *reinterpret_cast<float2*>(ex + (r0 + 8) * 66 + cb);
                __half2 lo = __floats2half2_rn(
                    ulo.x * fmaxf(acc[mi][ni][0], 0.f),
                    ulo.y * fmaxf(acc[mi][ni][1], 0.f));
                __half2 hi = __floats2half2_rn(
                    uhi.x * fmaxf(acc[mi][ni][2], 0.f),
                    uhi.y * fmaxf(acc[mi][ni][3], 0.f));
                *reinterpret_cast<uint32_t*>(Og + (size_t)r0 * 2048 + cb) =
                    *reinterpret_cast<uint32_t*>(&lo);
                *reinterpret_cast<uint32_t*>(Og + (size_t)(r0 + 8) * 2048 + cb) =
                    *reinterpret_cast<uint32_t*>(&hi);
            }
        }
    }
}

// ---------------------------------------------------------------------------
// GEMM2: 128x128 CTA tile, warps 2Mx2N, fp32 out.
// ---------------------------------------------------------------------------
__global__ void __launch_bounds__(128, 2)
gemm2(const __half* __restrict__ X, const __half* __restrict__ W2h,
      float* __restrict__ C)
{
    extern __shared__ __align__(16) char smem[];
    const int tid = threadIdx.x;
    const int wid = tid >> 5, lane = tid & 31;
    const int g = lane >> 2, tg = lane & 3;
    const int wm = wid & 1, wn = wid >> 1;
    const int nt = blockIdx.x, tt = blockIdx.y, e = blockIdx.z;
    constexpr int WN = 2048;

    const __half* Ag = X + (size_t)(e * 1024 + tt * 128) * KD;
    const uint32_t sbase = smem_u32(smem);

    const int cr = tid >> 3, cc = tid & 7;
    const uint32_t cdstA = (uint32_t)(cr * ROW_A + cc * 16);
    const int cr2 = tid >> 4, cc2 = tid & 15;
    const uint32_t cdstB = (uint32_t)(cr2 * ROW_BB + cc2 * 16);
    const __half* Bg = W2h + (size_t)e * KD * WN + nt * 128 + cc2 * 8;

    auto load_stage = [&](int buf, int kt) {
        const uint32_t sa = sbase + (uint32_t)buf * STAGE_B;
        const uint32_t sb = sa + TILE_A;
        const __half* a = Ag + kt * 64;
#pragma unroll
        for (int j = 0; j < 8; j++)
            CP16(sa + cdstA + (uint32_t)(j * 16 * ROW_A),
                 a + (size_t)(cr + j * 16) * KD + cc * 8);
        const __half* b = Bg + (size_t)(kt * 64 + cr2) * WN;
#pragma unroll
        for (int j = 0; j < 8; j++)
            CP16(sb + cdstB + (uint32_t)(j * 8 * ROW_BB),
                 b + (size_t)(j * 8) * WN);
        CP_COMMIT();
    };

    const uint32_t abase = (uint32_t)(wm * 64 * ROW_A) + ldsm_offA(lane);
    const uint32_t bbase = (uint32_t)(wn * 128) + ldsm_offB_T(lane) + TILE_A;

    float acc[4][8][4];
#pragma unroll
    for (int mi = 0; mi < 4; mi++)
#pragma unroll
        for (int ni = 0; ni < 8; ni++)
#pragma unroll
            for (int q = 0; q < 4; q++) acc[mi][ni][q] = 0.f;

    uint32_t af[2][4][4], bf[2][8][2];
    constexpr int NKT = KD / 64;   // 32
    MAINLOOP();

    float* Cg = C + (size_t)(e * 1024 + tt * 128) * WN + nt * 128;
#pragma unroll
    for (int mi = 0; mi < 4; mi++) {
        const int r0 = wm * 64 + mi * 16 + g;
#pragma unroll
        for (int ni = 0; ni < 8; ni++) {
            const int cb = wn * 64 + ni * 8 + tg * 2;
            float2 lo = make_float2(acc[mi][ni][0], acc[mi][ni][1]);
            float2 hi = make_float2(acc[mi][ni][2], acc[mi][ni][3]);
            *reinterpret_cast<float2*>(Cg + (size_t)r0 * WN + cb) = lo;
            *reinterpret_cast<float2*>(Cg + (size_t)(r0 + 8) * WN + cb) = hi;
        }
    }
}

// ---------------------------------------------------------------------------
// Merged pre-pass: rounds h, W1, W2 to fp16 in one launch (DRAM-floor bound).
// ---------------------------------------------------------------------------
static constexpr size_t N4_H  = 8192ull * 2048 / 4;          //  4194304
static constexpr size_t N4_W1 = 8ull * 2048 * 4096 / 4;      // 16777216
static constexpr size_t N4_W2 = 8ull * 2048 * 2048 / 4;      //  8388608
static constexpr size_t N4_ALL = N4_H + N4_W1 + N4_W2;       // 29360128

__global__ void __launch_bounds__(256)
round_all(__half* __restrict__ hh, const float* __restrict__ h,
          __half* __restrict__ w1h, const float* __restrict__ w1,
          __half* __restrict__ w2h, const float* __restrict__ w2)
{
    size_t i = (size_t)blockIdx.x * blockDim.x + threadIdx.x;   // f4 index
    const float* src;
    __half* dst;
    if (i < N4_H)              { src = h;  dst = hh; }
    else if (i < N4_H + N4_W1) { src = w1; dst = w1h; i -= N4_H; }
    else                       { src = w2; dst = w2h; i -= N4_H + N4_W1; }
    const float4 v = *reinterpret_cast<const float4*>(src + i * 4);
    __half2 lo = __floats2half2_rn(v.x, v.y);
    __half2 hi = __floats2half2_rn(v.z, v.w);
    uint2 o = make_uint2(*reinterpret_cast<uint32_t*>(&lo),
                         *reinterpret_cast<uint32_t*>(&hi));
    *reinterpret_cast<uint2*>(dst + i * 4) = o;
}

extern "C" void kernel_launch(void* const* d_in, const int* in_sizes, int n_in,
                              void* d_out, int out_size) {
    (void)in_sizes; (void)n_in; (void)out_size;
    const float* h  = (const float*)d_in[0];
    const float* w1 = (const float*)d_in[1];
    const float* w2 = (const float*)d_in[2];
    float* out = (float*)d_out;

    __half *act, *hh, *w1h, *w2h;
    cudaGetSymbolAddress((void**)&act, g_act);
    cudaGetSymbolAddress((void**)&hh,  g_hh);
    cudaGetSymbolAddress((void**)&w1h, g_w1h);
    cudaGetSymbolAddress((void**)&w2h, g_w2h);

    cudaFuncSetAttribute(gemm1_act,
                         cudaFuncAttributeMaxDynamicSharedMemorySize, SMEM_TOTAL);
    cudaFuncSetAttribute(gemm2,
                         cudaFuncAttributeMaxDynamicSharedMemorySize, SMEM_TOTAL);

    round_all<<<(unsigned)(N4_ALL / 256), 256>>>(hh, h, w1h, w1, w2h, w2);
    gemm1_act<<<dim3(32, 8, 8), 128, SMEM_TOTAL>>>(hh, w1h, act);
    gemm2<<<dim3(16, 8, 8), 128, SMEM_TOTAL>>>(act, w2h, out);
}